// round 16
// baseline (speedup 1.0000x reference)
#include <cuda_runtime.h>
#include <cuda_bf16.h>
#include <math.h>
#include <stdint.h>

// Problem constants
#define Bsz   2
#define SEQ   2048
#define DMODEL 1024
#define NH    16
#define HD    64
#define ROWS  (Bsz*SEQ)          // 4096
#define SCALE 0.03125f
#define LOG2E 1.4426950408889634f
#define SS (SCALE * LOG2E)

// ---------------- scratch ----------------
__device__ __align__(128) float g_y2[(size_t)ROWS * DMODEL];
__device__ __align__(128) __nv_bfloat16 g_xh [(size_t)ROWS * DMODEL];
__device__ __align__(128) __nv_bfloat16 g_xl [(size_t)ROWS * DMODEL];
__device__ __align__(128) __nv_bfloat16 g_wqh[(size_t)3 * DMODEL * DMODEL];
__device__ __align__(128) __nv_bfloat16 g_wql[(size_t)3 * DMODEL * DMODEL];
__device__ __align__(128) __nv_bfloat16 g_woh[(size_t)DMODEL * DMODEL];
__device__ __align__(128) __nv_bfloat16 g_wol[(size_t)DMODEL * DMODEL];
__device__ __align__(128) __nv_bfloat16 g_y1h[(size_t)ROWS * DMODEL];
__device__ __align__(128) __nv_bfloat16 g_y1l[(size_t)ROWS * DMODEL];
__device__ __align__(128) __nv_bfloat16 g_qb[(size_t)Bsz * NH * SEQ * HD];
__device__ __align__(128) __nv_bfloat16 g_kb[(size_t)Bsz * NH * SEQ * HD];
__device__ __align__(128) __nv_bfloat16 g_vt[(size_t)Bsz * NH * HD * SEQ];  // V^T [bh][d][s]

// ---------------- helpers ----------------
__device__ __forceinline__ unsigned smem_u32(const void* p) {
    unsigned a;
    asm("{ .reg .u64 t; cvta.to.shared.u64 t, %1; cvt.u32.u64 %0, t; }" : "=r"(a) : "l"(p));
    return a;
}
__device__ __forceinline__ void cp_async16(unsigned dst, const void* src) {
    asm volatile("cp.async.cg.shared.global [%0], [%1], 16;\n" :: "r"(dst), "l"(src));
}
__device__ __forceinline__ void cp_commit() { asm volatile("cp.async.commit_group;\n"); }
template<int N> __device__ __forceinline__ void cp_wait() {
    asm volatile("cp.async.wait_group %0;\n" :: "n"(N));
}
__device__ __forceinline__ float ex2(float x) {
    float r;
    asm("ex2.approx.ftz.f32 %0, %1;" : "=f"(r) : "f"(x));
    return r;
}
__device__ __forceinline__ void mma_bf16(float* c, unsigned a0, unsigned a1, unsigned a2, unsigned a3,
                                         unsigned b0, unsigned b1) {
    asm volatile(
        "mma.sync.aligned.m16n8k16.row.col.f32.bf16.bf16.f32 "
        "{%0,%1,%2,%3}, {%4,%5,%6,%7}, {%8,%9}, {%0,%1,%2,%3};"
        : "+f"(c[0]), "+f"(c[1]), "+f"(c[2]), "+f"(c[3])
        : "r"(a0), "r"(a1), "r"(a2), "r"(a3), "r"(b0), "r"(b1));
}
__device__ __forceinline__ void ldsm_x4(unsigned* r, unsigned addr) {
    asm volatile("ldmatrix.sync.aligned.m8n8.x4.shared.b16 {%0,%1,%2,%3}, [%4];"
        : "=r"(r[0]), "=r"(r[1]), "=r"(r[2]), "=r"(r[3]) : "r"(addr));
}
__device__ __forceinline__ unsigned pack_bf16(float lo, float hi) {
    __nv_bfloat162 t = __floats2bfloat162_rn(lo, hi);
    return *(unsigned*)&t;
}
__device__ __forceinline__ unsigned pack_raw2(const __nv_bfloat16* p) {
    unsigned short a = *(const unsigned short*)p;
    unsigned short b = *(const unsigned short*)(p + 1);
    return (unsigned)a | ((unsigned)b << 16);
}

// ---------------- HMMA split-bf16 GEMM: 256 thr, 8 warps, BK=64, 3-stage, ldmatrix,
//                  pass-ordered MMA issue (16 independent MMAs per pass) ----------------
#define GP64 144
#define TILE64 (128 * GP64)
#define G_B_H (2 * TILE64)
#define STG64 (4 * TILE64)
#define NSTG 3

template<int MODE>
__global__ __launch_bounds__(256, 1)
void gemm_mma(const __nv_bfloat16* __restrict__ Ah, const __nv_bfloat16* __restrict__ Al,
              const __nv_bfloat16* __restrict__ Bh, const __nv_bfloat16* __restrict__ Bl,
              const float* __restrict__ bias, float* __restrict__ C,
              __nv_bfloat16* __restrict__ Qb, __nv_bfloat16* __restrict__ Kb,
              __nv_bfloat16* __restrict__ Vt,
              int N, int K)
{
    extern __shared__ char dsm[];
    const int tid = threadIdx.x;
    const int wid = tid >> 5;
    const int lid = tid & 31;
    const int wm = wid & 3;
    const int wn = wid >> 2;
    const int bm = blockIdx.y * 128;
    const int bn = blockIdx.x * 128;
    const int gq = lid >> 2;
    const int gr = lid & 3;

    const unsigned dsmu = smem_u32(dsm);
    unsigned aOff[2], bOff[4];
    #pragma unroll
    for (int mi = 0; mi < 2; mi++)
        aOff[mi] = (unsigned)((wm * 32 + mi * 16 + (lid & 15)) * GP64 + ((lid >> 4) * 16));
    #pragma unroll
    for (int np = 0; np < 4; np++)
        bOff[np] = (unsigned)((wn * 64 + np * 16 + (lid & 7) + ((lid >> 4) & 1) * 8) * GP64
                              + (((lid >> 3) & 1) * 16));

    float acc[2][8][4];
    #pragma unroll
    for (int mi = 0; mi < 2; mi++)
        #pragma unroll
        for (int ni = 0; ni < 8; ni++)
            #pragma unroll
            for (int e = 0; e < 4; e++) acc[mi][ni][e] = 0.f;

    const int KITER = K / 64;

    auto prefetch = [&](int it, int s) {
        const int kt = it * 64;
        char* base = dsm + s * STG64;
        #pragma unroll
        for (int p = 0; p < 4; p++) {
            int idx = p * 256 + tid;
            int r = idx >> 3, c = idx & 7;
            unsigned dst = smem_u32(base + r * GP64 + c * 16);
            const size_t ga = (size_t)(bm + r) * K + kt + c * 8;
            const size_t gb = (size_t)(bn + r) * K + kt + c * 8;
            cp_async16(dst,              Ah + ga);
            cp_async16(dst + TILE64,     Al + ga);
            cp_async16(dst + 2 * TILE64, Bh + gb);
            cp_async16(dst + 3 * TILE64, Bl + gb);
        }
    };

    prefetch(0, 0); cp_commit();
    prefetch(1, 1); cp_commit();

    for (int i = 0; i < KITER; i++) {
        cp_wait<1>();
        __syncthreads();
        if (i + 2 < KITER) prefetch(i + 2, (i + 2) % NSTG);
        cp_commit();

        const unsigned sAu = dsmu + (i % NSTG) * STG64;
        const unsigned sBu = sAu + G_B_H;

        #pragma unroll
        for (int ks = 0; ks < 4; ks++) {
            const unsigned kb = ks * 32;
            // load ALL fragments for this ks-step
            unsigned aH[2][4], aL[2][4], bH[4][4], bL[4][4];
            #pragma unroll
            for (int mi = 0; mi < 2; mi++) {
                ldsm_x4(aH[mi], sAu + aOff[mi] + kb);
                ldsm_x4(aL[mi], sAu + TILE64 + aOff[mi] + kb);
            }
            #pragma unroll
            for (int np = 0; np < 4; np++) {
                ldsm_x4(bH[np], sBu + bOff[np] + kb);
                ldsm_x4(bL[np], sBu + TILE64 + bOff[np] + kb);
            }
            // pass 1: Ah*Bh -- 16 independent MMAs
            #pragma unroll
            for (int np = 0; np < 4; np++)
                #pragma unroll
                for (int q = 0; q < 2; q++)
                    #pragma unroll
                    for (int mi = 0; mi < 2; mi++)
                        mma_bf16(acc[mi][2 * np + q], aH[mi][0], aH[mi][1], aH[mi][2], aH[mi][3],
                                 bH[np][2 * q], bH[np][2 * q + 1]);
            // pass 2: Ah*Bl -- 16 independent MMAs
            #pragma unroll
            for (int np = 0; np < 4; np++)
                #pragma unroll
                for (int q = 0; q < 2; q++)
                    #pragma unroll
                    for (int mi = 0; mi < 2; mi++)
                        mma_bf16(acc[mi][2 * np + q], aH[mi][0], aH[mi][1], aH[mi][2], aH[mi][3],
                                 bL[np][2 * q], bL[np][2 * q + 1]);
            // pass 3: Al*Bh -- 16 independent MMAs
            #pragma unroll
            for (int np = 0; np < 4; np++)
                #pragma unroll
                for (int q = 0; q < 2; q++)
                    #pragma unroll
                    for (int mi = 0; mi < 2; mi++)
                        mma_bf16(acc[mi][2 * np + q], aL[mi][0], aL[mi][1], aL[mi][2], aL[mi][3],
                                 bH[np][2 * q], bH[np][2 * q + 1]);
        }
        __syncthreads();
    }

    if (MODE == 0) {
        #pragma unroll
        for (int mi = 0; mi < 2; mi++) {
            const int row = bm + wm * 32 + mi * 16 + gq;
            #pragma unroll
            for (int ni = 0; ni < 8; ni++) {
                const int col = bn + wn * 64 + ni * 8 + gr * 2;
                C[(size_t)row * N + col]           = acc[mi][ni][0] + bias[col];
                C[(size_t)row * N + col + 1]       = acc[mi][ni][1] + bias[col + 1];
                C[(size_t)(row + 8) * N + col]     = acc[mi][ni][2] + bias[col];
                C[(size_t)(row + 8) * N + col + 1] = acc[mi][ni][3] + bias[col + 1];
            }
        }
    } else {
        #pragma unroll
        for (int mi = 0; mi < 2; mi++) {
            const int row = bm + wm * 32 + mi * 16 + gq;
            const int s0 = row & (SEQ - 1);
            const int bidx = row >> 11;
            #pragma unroll
            for (int ni = 0; ni < 8; ni++) {
                const int col = bn + wn * 64 + ni * 8 + gr * 2;
                const float bb0 = bias[col], bb1 = bias[col + 1];
                float a0 = acc[mi][ni][0] + bb0, b0v = acc[mi][ni][1] + bb1;
                float a1 = acc[mi][ni][2] + bb0, b1v = acc[mi][ni][3] + bb1;
                const int part = col >> 10;
                const int c1 = col & (DMODEL - 1);
                const int h = c1 >> 6, d = c1 & (HD - 1);
                const int bh = bidx * NH + h;
                if (part == 2) {
                    const size_t o0 = ((size_t)bh * HD + d) * SEQ + s0;
                    Vt[o0]           = __float2bfloat16(a0);
                    Vt[o0 + SEQ]     = __float2bfloat16(b0v);
                    Vt[o0 + 8]       = __float2bfloat16(a1);
                    Vt[o0 + SEQ + 8] = __float2bfloat16(b1v);
                } else {
                    float va0 = a0, vb0 = b0v, va1 = a1, vb1 = b1v;
                    if (d < 32) {
                        const int i = d >> 1;
                        const float invf = exp2f(-0.8304820237218406f * (float)i);
                        float sn0, cs0, sn1, cs1;
                        sincosf((float)s0 * invf, &sn0, &cs0);
                        sincosf((float)(s0 + 8) * invf, &sn1, &cs1);
                        va0 = a0 * cs0 - b0v * sn0;  vb0 = b0v * cs0 + a0 * sn0;
                        va1 = a1 * cs1 - b1v * sn1;  vb1 = b1v * cs1 + a1 * sn1;
                    }
                    __nv_bfloat16* dst = (part == 0) ? Qb : Kb;
                    const size_t o = ((size_t)bh * SEQ + s0) * HD + d;
                    dst[o]            = __float2bfloat16(va0);
                    dst[o + 1]        = __float2bfloat16(vb0);
                    dst[o + 8 * HD]     = __float2bfloat16(va1);
                    dst[o + 8 * HD + 1] = __float2bfloat16(vb1);
                }
            }
        }
    }
}

// ---------------- prep kernels ----------------
__global__ __launch_bounds__(256)
void split_x(const float* __restrict__ X, __nv_bfloat16* __restrict__ Xh,
             __nv_bfloat16* __restrict__ Xl)
{
    int i = blockIdx.x * 256 + threadIdx.x;
    float v = X[i];
    __nv_bfloat16 h = __float2bfloat16(v);
    Xh[i] = h;
    Xl[i] = __float2bfloat16(v - __bfloat162float(h));
}

__global__ __launch_bounds__(256)
void transpose_split(const float* __restrict__ W, __nv_bfloat16* __restrict__ Th,
                     __nv_bfloat16* __restrict__ Tl, int K, int N)
{
    __shared__ float t[32][33];
    const int n0 = blockIdx.x * 32, k0 = blockIdx.y * 32;
    const int tx = threadIdx.x & 31, ty = threadIdx.x >> 5;
    #pragma unroll
    for (int i = 0; i < 32; i += 8)
        t[ty + i][tx] = W[(size_t)(k0 + ty + i) * N + n0 + tx];
    __syncthreads();
    #pragma unroll
    for (int i = 0; i < 32; i += 8) {
        float v = t[tx][ty + i];
        __nv_bfloat16 h = __float2bfloat16(v);
        size_t o = (size_t)(n0 + ty + i) * K + k0 + tx;
        Th[o] = h;
        Tl[o] = __float2bfloat16(v - __bfloat162float(h));
    }
}

// ---------------- HMMA flash attention (ldmatrix fragment loads) ----------------
#define KP 144
#define ATILE (64 * KP)
#define ASTG (2 * ATILE)

__global__ __launch_bounds__(256, 1)
void attn_mma(const __nv_bfloat16* __restrict__ Qb, const __nv_bfloat16* __restrict__ Kb,
              const __nv_bfloat16* __restrict__ Vt, const float* __restrict__ x,
              __nv_bfloat16* __restrict__ y1h, __nv_bfloat16* __restrict__ y1l)
{
    extern __shared__ char dsm[];

    const int bh = blockIdx.y;
    const int q0 = blockIdx.x * 128;
    const int tid = threadIdx.x;
    const int wid = tid >> 5;
    const int lid = tid & 31;
    const int gq = lid >> 2;
    const int gr = lid & 3;

    const unsigned dsmu = smem_u32(dsm);
    unsigned kOff[4];
    #pragma unroll
    for (int np = 0; np < 4; np++)
        kOff[np] = (unsigned)((np * 16 + (lid & 7) + ((lid >> 4) & 1) * 8) * KP
                              + (((lid >> 3) & 1) * 16));

    const __nv_bfloat16* Kbase = Kb + (size_t)bh * SEQ * HD;
    const __nv_bfloat16* Vbase = Vt + (size_t)bh * HD * SEQ;

    auto prefetch = [&](int it, int s) {
        const int kt = it * 64;
        char* base = dsm + s * ASTG;
        #pragma unroll
        for (int p = 0; p < 4; p++) {
            int idx = p * 256 + tid;
            if (idx < 512) {
                int r = idx >> 3, c = idx & 7;
                cp_async16(smem_u32(base + r * KP + c * 16),
                           Kbase + (size_t)(kt + r) * HD + c * 8);
            } else {
                int i2 = idx - 512;
                int d = i2 >> 3, c = i2 & 7;
                cp_async16(smem_u32(base + ATILE + d * KP + c * 16),
                           Vbase + (size_t)d * SEQ + kt + c * 8);
            }
        }
    };

    unsigned qa[4][4];
    {
        const __nv_bfloat16* Qr  = Qb + ((size_t)bh * SEQ + q0 + wid * 16 + gq) * HD;
        const __nv_bfloat16* Qr8 = Qr + 8 * HD;
        #pragma unroll
        for (int ks = 0; ks < 4; ks++) {
            const int k0 = ks * 16 + gr * 2;
            qa[ks][0] = pack_raw2(Qr  + k0);
            qa[ks][1] = pack_raw2(Qr8 + k0);
            qa[ks][2] = pack_raw2(Qr  + k0 + 8);
            qa[ks][3] = pack_raw2(Qr8 + k0 + 8);
        }
    }

    float ao[8][4];
    #pragma unroll
    for (int nd = 0; nd < 8; nd++)
        #pragma unroll
        for (int e = 0; e < 4; e++) ao[nd][e] = 0.f;
    float m0 = -1e30f, m1 = -1e30f, l0 = 0.f, l1 = 0.f;

    prefetch(0, 0); cp_commit();

    int buf = 0;
    for (int t = 0; t < SEQ / 64; t++) {
        if (t + 1 < SEQ / 64) prefetch(t + 1, buf ^ 1);
        cp_commit();
        cp_wait<1>();
        __syncthreads();

        const unsigned sKu = dsmu + buf * ASTG;
        const unsigned sVu = sKu + ATILE;

        float sc[8][4];
        #pragma unroll
        for (int ni = 0; ni < 8; ni++)
            #pragma unroll
            for (int e = 0; e < 4; e++) sc[ni][e] = 0.f;

        #pragma unroll
        for (int ks = 0; ks < 4; ks++) {
            const unsigned kb = ks * 32;
            #pragma unroll
            for (int np = 0; np < 4; np++) {
                unsigned bb[4];
                ldsm_x4(bb, sKu + kOff[np] + kb);
                mma_bf16(sc[2 * np],     qa[ks][0], qa[ks][1], qa[ks][2], qa[ks][3], bb[0], bb[1]);
                mma_bf16(sc[2 * np + 1], qa[ks][0], qa[ks][1], qa[ks][2], qa[ks][3], bb[2], bb[3]);
            }
        }

        float tm0 = -1e30f, tm1 = -1e30f;
        #pragma unroll
        for (int ni = 0; ni < 8; ni++) {
            tm0 = fmaxf(tm0, fmaxf(sc[ni][0], sc[ni][1]));
            tm1 = fmaxf(tm1, fmaxf(sc[ni][2], sc[ni][3]));
        }
        tm0 *= SS; tm1 *= SS;
        tm0 = fmaxf(tm0, __shfl_xor_sync(0xffffffffu, tm0, 1));
        tm0 = fmaxf(tm0, __shfl_xor_sync(0xffffffffu, tm0, 2));
        tm1 = fmaxf(tm1, __shfl_xor_sync(0xffffffffu, tm1, 1));
        tm1 = fmaxf(tm1, __shfl_xor_sync(0xffffffffu, tm1, 2));

        float m0n = fmaxf(m0, tm0), m1n = fmaxf(m1, tm1);
        float c0 = ex2(m0 - m0n), c1 = ex2(m1 - m1n);
        m0 = m0n; m1 = m1n;
        l0 *= c0; l1 *= c1;
        #pragma unroll
        for (int nd = 0; nd < 8; nd++) {
            ao[nd][0] *= c0; ao[nd][1] *= c0;
            ao[nd][2] *= c1; ao[nd][3] *= c1;
        }

        #pragma unroll
        for (int ni = 0; ni < 8; ni++) {
            sc[ni][0] = ex2(sc[ni][0] * SS - m0);
            sc[ni][1] = ex2(sc[ni][1] * SS - m0);
            sc[ni][2] = ex2(sc[ni][2] * SS - m1);
            sc[ni][3] = ex2(sc[ni][3] * SS - m1);
            l0 += sc[ni][0] + sc[ni][1];
            l1 += sc[ni][2] + sc[ni][3];
        }

        unsigned pa[4][4];
        #pragma unroll
        for (int ki = 0; ki < 4; ki++) {
            pa[ki][0] = pack_bf16(sc[2 * ki][0],     sc[2 * ki][1]);
            pa[ki][1] = pack_bf16(sc[2 * ki][2],     sc[2 * ki][3]);
            pa[ki][2] = pack_bf16(sc[2 * ki + 1][0], sc[2 * ki + 1][1]);
            pa[ki][3] = pack_bf16(sc[2 * ki + 1][2], sc[2 * ki + 1][3]);
        }

        #pragma unroll
        for (int ki = 0; ki < 4; ki++) {
            const unsigned kb = ki * 32;
            #pragma unroll
            for (int np = 0; np < 4; np++) {
                unsigned bb[4];
                ldsm_x4(bb, sVu + kOff[np] + kb);
                mma_bf16(ao[2 * np],     pa[ki][0], pa[ki][1], pa[ki][2], pa[ki][3], bb[0], bb[1]);
                mma_bf16(ao[2 * np + 1], pa[ki][0], pa[ki][1], pa[ki][2], pa[ki][3], bb[2], bb[3]);
            }
        }

        __syncthreads();
        buf ^= 1;
    }

    l0 += __shfl_xor_sync(0xffffffffu, l0, 1);
    l0 += __shfl_xor_sync(0xffffffffu, l0, 2);
    l1 += __shfl_xor_sync(0xffffffffu, l1, 1);
    l1 += __shfl_xor_sync(0xffffffffu, l1, 2);
    const float inv0 = 1.f / l0, inv1 = 1.f / l1;

    const int b = bh / NH, h = bh % NH;
    const int r0 = q0 + wid * 16 + gq;
    const size_t off0 = ((size_t)b * SEQ + r0) * DMODEL + h * HD;
    const size_t off1 = off0 + 8 * DMODEL;

    #pragma unroll
    for (int nd = 0; nd < 8; nd++) {
        const int col = nd * 8 + gr * 2;
        #pragma unroll
        for (int e = 0; e < 2; e++) {
            float v0 = ao[nd][e]     * inv0 + x[off0 + col + e];
            float v1 = ao[nd][2 + e] * inv1 + x[off1 + col + e];
            __nv_bfloat16 h0 = __float2bfloat16(v0);
            __nv_bfloat16 h1 = __float2bfloat16(v1);
            y1h[off0 + col + e] = h0;
            y1h[off1 + col + e] = h1;
            y1l[off0 + col + e] = __float2bfloat16(v0 - __bfloat162float(h0));
            y1l[off1 + col + e] = __float2bfloat16(v1 - __bfloat162float(h1));
        }
    }
}

// ---------------- LayerNorm ----------------
__inline__ __device__ float warpsum(float v) {
    #pragma unroll
    for (int o = 16; o; o >>= 1) v += __shfl_xor_sync(0xffffffffu, v, o);
    return v;
}

__global__ __launch_bounds__(256)
void ln_kernel(const float* __restrict__ Y, const float* __restrict__ gamma,
               const float* __restrict__ beta, float* __restrict__ out)
{
    const int row = blockIdx.x;
    const int t = threadIdx.x;
    const float* yr = Y + (size_t)row * DMODEL;

    float vals[4];
    float s = 0.f, s2 = 0.f;
    #pragma unroll
    for (int k = 0; k < 4; k++) {
        float v = yr[t + k * 256];
        vals[k] = v;
        s += v; s2 += v * v;
    }
    s = warpsum(s); s2 = warpsum(s2);

    __shared__ float sh[16];
    int w = t >> 5, ln = t & 31;
    if (ln == 0) { sh[w] = s; sh[8 + w] = s2; }
    __syncthreads();
    if (t == 0) {
        float a = 0.f, a2 = 0.f;
        #pragma unroll
        for (int i = 0; i < 8; i++) { a += sh[i]; a2 += sh[8 + i]; }
        sh[0] = a; sh[8] = a2;
    }
    __syncthreads();
    const float mu  = sh[0] * (1.f / DMODEL);
    const float var = sh[8] * (1.f / DMODEL) - mu * mu;
    const float inv = rsqrtf(var + 1e-5f);

    #pragma unroll
    for (int k = 0; k < 4; k++) {
        int c = t + k * 256;
        out[(size_t)row * DMODEL + c] = (vals[k] - mu) * inv * gamma[c] + beta[c];
    }
}

// ---------------- launch ----------------
extern "C" void kernel_launch(void* const* d_in, const int* in_sizes, int n_in,
                              void* d_out, int out_size)
{
    const float* x      = (const float*)d_in[0];
    const float* w_qkv  = (const float*)d_in[1];
    const float* b_qkv  = (const float*)d_in[2];
    const float* w_out  = (const float*)d_in[3];
    const float* b_out  = (const float*)d_in[4];
    const float* gammap = (const float*)d_in[5];
    const float* betap  = (const float*)d_in[6];
    float* out = (float*)d_out;

    float *y2;
    __nv_bfloat16 *xh, *xl, *wqh, *wql, *woh, *wol, *y1h, *y1l, *qb, *kb, *vt;
    cudaGetSymbolAddress((void**)&y2, g_y2);
    cudaGetSymbolAddress((void**)&xh, g_xh);
    cudaGetSymbolAddress((void**)&xl, g_xl);
    cudaGetSymbolAddress((void**)&wqh, g_wqh);
    cudaGetSymbolAddress((void**)&wql, g_wql);
    cudaGetSymbolAddress((void**)&woh, g_woh);
    cudaGetSymbolAddress((void**)&wol, g_wol);
    cudaGetSymbolAddress((void**)&y1h, g_y1h);
    cudaGetSymbolAddress((void**)&y1l, g_y1l);
    cudaGetSymbolAddress((void**)&qb, g_qb);
    cudaGetSymbolAddress((void**)&kb, g_kb);
    cudaGetSymbolAddress((void**)&vt, g_vt);

    cudaFuncSetAttribute(gemm_mma<0>, cudaFuncAttributeMaxDynamicSharedMemorySize, NSTG * STG64);
    cudaFuncSetAttribute(gemm_mma<1>, cudaFuncAttributeMaxDynamicSharedMemorySize, NSTG * STG64);
    cudaFuncSetAttribute(attn_mma, cudaFuncAttributeMaxDynamicSharedMemorySize, 2 * ASTG);

    // operand prep
    split_x<<<(ROWS * DMODEL) / 256, 256>>>(x, xh, xl);
    transpose_split<<<dim3(3 * DMODEL / 32, DMODEL / 32), 256>>>(w_qkv, wqh, wql, DMODEL, 3 * DMODEL);
    transpose_split<<<dim3(DMODEL / 32, DMODEL / 32), 256>>>(w_out, woh, wol, DMODEL, DMODEL);

    // 1. QKV projection + fused bias/RoPE/split
    gemm_mma<1><<<dim3(3 * DMODEL / 128, ROWS / 128), 256, NSTG * STG64>>>(
        xh, xl, wqh, wql, b_qkv, nullptr, qb, kb, vt, 3 * DMODEL, DMODEL);

    // 2. HMMA flash attention + residual -> y1 hi/lo
    dim3 ga(SEQ / 128, Bsz * NH);
    attn_mma<<<ga, 256, 2 * ASTG>>>(qb, kb, vt, x, y1h, y1l);

    // 3. output projection
    gemm_mma<0><<<dim3(DMODEL / 128, ROWS / 128), 256, NSTG * STG64>>>(
        y1h, y1l, woh, wol, b_out, y2, nullptr, nullptr, nullptr, DMODEL, DMODEL);

    // 4. layernorm
    ln_kernel<<<ROWS, 256>>>(y2, gammap, betap, out);
}

// round 17
// speedup vs baseline: 1.3396x; 1.3396x over previous
#include <cuda_runtime.h>
#include <cuda_bf16.h>
#include <math.h>
#include <stdint.h>

// Problem constants
#define Bsz   2
#define SEQ   2048
#define DMODEL 1024
#define NH    16
#define HD    64
#define ROWS  (Bsz*SEQ)          // 4096
#define SCALE 0.03125f
#define LOG2E 1.4426950408889634f
#define SS (SCALE * LOG2E)

// ---------------- scratch ----------------
__device__ __align__(128) float g_y2[(size_t)ROWS * DMODEL];
__device__ __align__(128) __nv_bfloat16 g_xh [(size_t)ROWS * DMODEL];
__device__ __align__(128) __nv_bfloat16 g_wqh[(size_t)3 * DMODEL * DMODEL];
__device__ __align__(128) __nv_bfloat16 g_woh[(size_t)DMODEL * DMODEL];
__device__ __align__(128) __nv_bfloat16 g_wol[(size_t)DMODEL * DMODEL];
__device__ __align__(128) __nv_bfloat16 g_y1h[(size_t)ROWS * DMODEL];
__device__ __align__(128) __nv_bfloat16 g_y1l[(size_t)ROWS * DMODEL];
__device__ __align__(128) __nv_bfloat16 g_qb[(size_t)Bsz * NH * SEQ * HD];
__device__ __align__(128) __nv_bfloat16 g_kb[(size_t)Bsz * NH * SEQ * HD];
__device__ __align__(128) __nv_bfloat16 g_vt[(size_t)Bsz * NH * HD * SEQ];  // V^T [bh][d][s]

// ---------------- helpers ----------------
__device__ __forceinline__ unsigned smem_u32(const void* p) {
    unsigned a;
    asm("{ .reg .u64 t; cvta.to.shared.u64 t, %1; cvt.u32.u64 %0, t; }" : "=r"(a) : "l"(p));
    return a;
}
__device__ __forceinline__ void cp_async16(unsigned dst, const void* src) {
    asm volatile("cp.async.cg.shared.global [%0], [%1], 16;\n" :: "r"(dst), "l"(src));
}
__device__ __forceinline__ void cp_commit() { asm volatile("cp.async.commit_group;\n"); }
template<int N> __device__ __forceinline__ void cp_wait() {
    asm volatile("cp.async.wait_group %0;\n" :: "n"(N));
}
__device__ __forceinline__ float ex2(float x) {
    float r;
    asm("ex2.approx.ftz.f32 %0, %1;" : "=f"(r) : "f"(x));
    return r;
}
__device__ __forceinline__ void mma_bf16(float* c, unsigned a0, unsigned a1, unsigned a2, unsigned a3,
                                         unsigned b0, unsigned b1) {
    asm volatile(
        "mma.sync.aligned.m16n8k16.row.col.f32.bf16.bf16.f32 "
        "{%0,%1,%2,%3}, {%4,%5,%6,%7}, {%8,%9}, {%0,%1,%2,%3};"
        : "+f"(c[0]), "+f"(c[1]), "+f"(c[2]), "+f"(c[3])
        : "r"(a0), "r"(a1), "r"(a2), "r"(a3), "r"(b0), "r"(b1));
}
__device__ __forceinline__ void ldsm_x4(unsigned* r, unsigned addr) {
    asm volatile("ldmatrix.sync.aligned.m8n8.x4.shared.b16 {%0,%1,%2,%3}, [%4];"
        : "=r"(r[0]), "=r"(r[1]), "=r"(r[2]), "=r"(r[3]) : "r"(addr));
}
__device__ __forceinline__ unsigned pack_bf16(float lo, float hi) {
    __nv_bfloat162 t = __floats2bfloat162_rn(lo, hi);
    return *(unsigned*)&t;
}
__device__ __forceinline__ unsigned pack_raw2(const __nv_bfloat16* p) {
    unsigned short a = *(const unsigned short*)p;
    unsigned short b = *(const unsigned short*)(p + 1);
    return (unsigned)a | ((unsigned)b << 16);
}

// ---------------- HMMA GEMM: 256 thr, 8 warps, BK=64, 3-stage, ldmatrix ----------------
// MODE 0: 3-pass split-bf16 (fp32-accurate), fp32 out + bias.
// MODE 1: 1-pass bf16, fused QKV epilogue (bias + RoPE -> Qb/Kb/Vt bf16).
#define GP64 144
#define TILE64 (128 * GP64)
#define NSTG 3
#define STG_S (4 * TILE64)       // split stage: Ah,Al,Bh,Bl
#define STG_F (2 * TILE64)       // fast stage:  Ah,Bh

template<int MODE>
__global__ __launch_bounds__(256, 1)
void gemm_mma(const __nv_bfloat16* __restrict__ Ah, const __nv_bfloat16* __restrict__ Al,
              const __nv_bfloat16* __restrict__ Bh, const __nv_bfloat16* __restrict__ Bl,
              const float* __restrict__ bias, float* __restrict__ C,
              __nv_bfloat16* __restrict__ Qb, __nv_bfloat16* __restrict__ Kb,
              __nv_bfloat16* __restrict__ Vt,
              int N, int K)
{
    constexpr int STG = (MODE == 0) ? STG_S : STG_F;
    extern __shared__ char dsm[];
    const int tid = threadIdx.x;
    const int wid = tid >> 5;
    const int lid = tid & 31;
    const int wm = wid & 3;
    const int wn = wid >> 2;
    const int bm = blockIdx.y * 128;
    const int bn = blockIdx.x * 128;
    const int gq = lid >> 2;
    const int gr = lid & 3;

    const unsigned dsmu = smem_u32(dsm);
    unsigned aOff[2], bOff[4];
    #pragma unroll
    for (int mi = 0; mi < 2; mi++)
        aOff[mi] = (unsigned)((wm * 32 + mi * 16 + (lid & 15)) * GP64 + ((lid >> 4) * 16));
    #pragma unroll
    for (int np = 0; np < 4; np++)
        bOff[np] = (unsigned)((wn * 64 + np * 16 + (lid & 7) + ((lid >> 4) & 1) * 8) * GP64
                              + (((lid >> 3) & 1) * 16));

    float acc[2][8][4];
    #pragma unroll
    for (int mi = 0; mi < 2; mi++)
        #pragma unroll
        for (int ni = 0; ni < 8; ni++)
            #pragma unroll
            for (int e = 0; e < 4; e++) acc[mi][ni][e] = 0.f;

    const int KITER = K / 64;
    const unsigned bOffTile = (MODE == 0) ? (2 * TILE64) : TILE64;  // B-hi tile offset in stage

    auto prefetch = [&](int it, int s) {
        const int kt = it * 64;
        char* base = dsm + s * STG;
        #pragma unroll
        for (int p = 0; p < 4; p++) {
            int idx = p * 256 + tid;
            int r = idx >> 3, c = idx & 7;
            unsigned dst = smem_u32(base + r * GP64 + c * 16);
            const size_t ga = (size_t)(bm + r) * K + kt + c * 8;
            const size_t gb = (size_t)(bn + r) * K + kt + c * 8;
            if (MODE == 0) {
                cp_async16(dst,              Ah + ga);
                cp_async16(dst + TILE64,     Al + ga);
                cp_async16(dst + 2 * TILE64, Bh + gb);
                cp_async16(dst + 3 * TILE64, Bl + gb);
            } else {
                cp_async16(dst,          Ah + ga);
                cp_async16(dst + TILE64, Bh + gb);
            }
        }
    };

    prefetch(0, 0); cp_commit();
    prefetch(1, 1); cp_commit();

    for (int i = 0; i < KITER; i++) {
        cp_wait<1>();
        __syncthreads();
        if (i + 2 < KITER) prefetch(i + 2, (i + 2) % NSTG);
        cp_commit();

        const unsigned sAu = dsmu + (i % NSTG) * STG;
        const unsigned sBu = sAu + bOffTile;

        #pragma unroll
        for (int ks = 0; ks < 4; ks++) {
            const unsigned kb = ks * 32;
            unsigned aH[2][4], bH[4][4];
            #pragma unroll
            for (int mi = 0; mi < 2; mi++)
                ldsm_x4(aH[mi], sAu + aOff[mi] + kb);
            #pragma unroll
            for (int np = 0; np < 4; np++)
                ldsm_x4(bH[np], sBu + bOff[np] + kb);

            if (MODE == 0) {
                unsigned aL[2][4], bL[4][4];
                #pragma unroll
                for (int mi = 0; mi < 2; mi++)
                    ldsm_x4(aL[mi], sAu + TILE64 + aOff[mi] + kb);
                #pragma unroll
                for (int np = 0; np < 4; np++)
                    ldsm_x4(bL[np], sBu + TILE64 + bOff[np] + kb);
                #pragma unroll
                for (int np = 0; np < 4; np++)
                    #pragma unroll
                    for (int q = 0; q < 2; q++)
                        #pragma unroll
                        for (int mi = 0; mi < 2; mi++) {
                            mma_bf16(acc[mi][2 * np + q], aH[mi][0], aH[mi][1], aH[mi][2], aH[mi][3],
                                     bH[np][2 * q], bH[np][2 * q + 1]);
                            mma_bf16(acc[mi][2 * np + q], aH[mi][0], aH[mi][1], aH[mi][2], aH[mi][3],
                                     bL[np][2 * q], bL[np][2 * q + 1]);
                            mma_bf16(acc[mi][2 * np + q], aL[mi][0], aL[mi][1], aL[mi][2], aL[mi][3],
                                     bH[np][2 * q], bH[np][2 * q + 1]);
                        }
            } else {
                #pragma unroll
                for (int np = 0; np < 4; np++)
                    #pragma unroll
                    for (int q = 0; q < 2; q++)
                        #pragma unroll
                        for (int mi = 0; mi < 2; mi++)
                            mma_bf16(acc[mi][2 * np + q], aH[mi][0], aH[mi][1], aH[mi][2], aH[mi][3],
                                     bH[np][2 * q], bH[np][2 * q + 1]);
            }
        }
        __syncthreads();
    }

    if (MODE == 0) {
        #pragma unroll
        for (int mi = 0; mi < 2; mi++) {
            const int row = bm + wm * 32 + mi * 16 + gq;
            #pragma unroll
            for (int ni = 0; ni < 8; ni++) {
                const int col = bn + wn * 64 + ni * 8 + gr * 2;
                C[(size_t)row * N + col]           = acc[mi][ni][0] + bias[col];
                C[(size_t)row * N + col + 1]       = acc[mi][ni][1] + bias[col + 1];
                C[(size_t)(row + 8) * N + col]     = acc[mi][ni][2] + bias[col];
                C[(size_t)(row + 8) * N + col + 1] = acc[mi][ni][3] + bias[col + 1];
            }
        }
    } else {
        #pragma unroll
        for (int mi = 0; mi < 2; mi++) {
            const int row = bm + wm * 32 + mi * 16 + gq;
            const int s0 = row & (SEQ - 1);
            const int bidx = row >> 11;
            #pragma unroll
            for (int ni = 0; ni < 8; ni++) {
                const int col = bn + wn * 64 + ni * 8 + gr * 2;
                const float bb0 = bias[col], bb1 = bias[col + 1];
                float a0 = acc[mi][ni][0] + bb0, b0v = acc[mi][ni][1] + bb1;
                float a1 = acc[mi][ni][2] + bb0, b1v = acc[mi][ni][3] + bb1;
                const int part = col >> 10;
                const int c1 = col & (DMODEL - 1);
                const int h = c1 >> 6, d = c1 & (HD - 1);
                const int bh = bidx * NH + h;
                if (part == 2) {
                    const size_t o0 = ((size_t)bh * HD + d) * SEQ + s0;
                    Vt[o0]           = __float2bfloat16(a0);
                    Vt[o0 + SEQ]     = __float2bfloat16(b0v);
                    Vt[o0 + 8]       = __float2bfloat16(a1);
                    Vt[o0 + SEQ + 8] = __float2bfloat16(b1v);
                } else {
                    float va0 = a0, vb0 = b0v, va1 = a1, vb1 = b1v;
                    if (d < 32) {
                        const int i = d >> 1;
                        const float invf = exp2f(-0.8304820237218406f * (float)i);
                        float sn0, cs0, sn1, cs1;
                        sincosf((float)s0 * invf, &sn0, &cs0);
                        sincosf((float)(s0 + 8) * invf, &sn1, &cs1);
                        va0 = a0 * cs0 - b0v * sn0;  vb0 = b0v * cs0 + a0 * sn0;
                        va1 = a1 * cs1 - b1v * sn1;  vb1 = b1v * cs1 + a1 * sn1;
                    }
                    __nv_bfloat16* dst = (part == 0) ? Qb : Kb;
                    const size_t o = ((size_t)bh * SEQ + s0) * HD + d;
                    dst[o]            = __float2bfloat16(va0);
                    dst[o + 1]        = __float2bfloat16(vb0);
                    dst[o + 8 * HD]     = __float2bfloat16(va1);
                    dst[o + 8 * HD + 1] = __float2bfloat16(vb1);
                }
            }
        }
    }
}

// ---------------- prep kernels ----------------
__global__ __launch_bounds__(256)
void to_bf16(const float* __restrict__ X, __nv_bfloat16* __restrict__ Xh)
{
    int i = blockIdx.x * 256 + threadIdx.x;
    Xh[i] = __float2bfloat16(X[i]);
}

template<bool LO>
__global__ __launch_bounds__(256)
void transpose_split(const float* __restrict__ W, __nv_bfloat16* __restrict__ Th,
                     __nv_bfloat16* __restrict__ Tl, int K, int N)
{
    __shared__ float t[32][33];
    const int n0 = blockIdx.x * 32, k0 = blockIdx.y * 32;
    const int tx = threadIdx.x & 31, ty = threadIdx.x >> 5;
    #pragma unroll
    for (int i = 0; i < 32; i += 8)
        t[ty + i][tx] = W[(size_t)(k0 + ty + i) * N + n0 + tx];
    __syncthreads();
    #pragma unroll
    for (int i = 0; i < 32; i += 8) {
        float v = t[tx][ty + i];
        __nv_bfloat16 h = __float2bfloat16(v);
        size_t o = (size_t)(n0 + ty + i) * K + k0 + tx;
        Th[o] = h;
        if (LO) Tl[o] = __float2bfloat16(v - __bfloat162float(h));
    }
}

// ---------------- HMMA flash attention (R15 version, unchanged) ----------------
#define KP 144
#define ATILE (64 * KP)
#define ASTG (2 * ATILE)

__global__ __launch_bounds__(256, 1)
void attn_mma(const __nv_bfloat16* __restrict__ Qb, const __nv_bfloat16* __restrict__ Kb,
              const __nv_bfloat16* __restrict__ Vt, const float* __restrict__ x,
              __nv_bfloat16* __restrict__ y1h, __nv_bfloat16* __restrict__ y1l)
{
    extern __shared__ char dsm[];

    const int bh = blockIdx.y;
    const int q0 = blockIdx.x * 128;
    const int tid = threadIdx.x;
    const int wid = tid >> 5;
    const int lid = tid & 31;
    const int gq = lid >> 2;
    const int gr = lid & 3;

    const unsigned dsmu = smem_u32(dsm);
    unsigned kOff[4];
    #pragma unroll
    for (int np = 0; np < 4; np++)
        kOff[np] = (unsigned)((np * 16 + (lid & 7) + ((lid >> 4) & 1) * 8) * KP
                              + (((lid >> 3) & 1) * 16));

    const __nv_bfloat16* Kbase = Kb + (size_t)bh * SEQ * HD;
    const __nv_bfloat16* Vbase = Vt + (size_t)bh * HD * SEQ;

    auto prefetch = [&](int it, int s) {
        const int kt = it * 64;
        char* base = dsm + s * ASTG;
        #pragma unroll
        for (int p = 0; p < 4; p++) {
            int idx = p * 256 + tid;
            if (idx < 512) {
                int r = idx >> 3, c = idx & 7;
                cp_async16(smem_u32(base + r * KP + c * 16),
                           Kbase + (size_t)(kt + r) * HD + c * 8);
            } else {
                int i2 = idx - 512;
                int d = i2 >> 3, c = i2 & 7;
                cp_async16(smem_u32(base + ATILE + d * KP + c * 16),
                           Vbase + (size_t)d * SEQ + kt + c * 8);
            }
        }
    };

    unsigned qa[4][4];
    {
        const __nv_bfloat16* Qr  = Qb + ((size_t)bh * SEQ + q0 + wid * 16 + gq) * HD;
        const __nv_bfloat16* Qr8 = Qr + 8 * HD;
        #pragma unroll
        for (int ks = 0; ks < 4; ks++) {
            const int k0 = ks * 16 + gr * 2;
            qa[ks][0] = pack_raw2(Qr  + k0);
            qa[ks][1] = pack_raw2(Qr8 + k0);
            qa[ks][2] = pack_raw2(Qr  + k0 + 8);
            qa[ks][3] = pack_raw2(Qr8 + k0 + 8);
        }
    }

    float ao[8][4];
    #pragma unroll
    for (int nd = 0; nd < 8; nd++)
        #pragma unroll
        for (int e = 0; e < 4; e++) ao[nd][e] = 0.f;
    float m0 = -1e30f, m1 = -1e30f, l0 = 0.f, l1 = 0.f;

    prefetch(0, 0); cp_commit();

    int buf = 0;
    for (int t = 0; t < SEQ / 64; t++) {
        if (t + 1 < SEQ / 64) prefetch(t + 1, buf ^ 1);
        cp_commit();
        cp_wait<1>();
        __syncthreads();

        const unsigned sKu = dsmu + buf * ASTG;
        const unsigned sVu = sKu + ATILE;

        float sc[8][4];
        #pragma unroll
        for (int ni = 0; ni < 8; ni++)
            #pragma unroll
            for (int e = 0; e < 4; e++) sc[ni][e] = 0.f;

        #pragma unroll
        for (int ks = 0; ks < 4; ks++) {
            const unsigned kb = ks * 32;
            #pragma unroll
            for (int np = 0; np < 4; np++) {
                unsigned bb[4];
                ldsm_x4(bb, sKu + kOff[np] + kb);
                mma_bf16(sc[2 * np],     qa[ks][0], qa[ks][1], qa[ks][2], qa[ks][3], bb[0], bb[1]);
                mma_bf16(sc[2 * np + 1], qa[ks][0], qa[ks][1], qa[ks][2], qa[ks][3], bb[2], bb[3]);
            }
        }

        float tm0 = -1e30f, tm1 = -1e30f;
        #pragma unroll
        for (int ni = 0; ni < 8; ni++) {
            tm0 = fmaxf(tm0, fmaxf(sc[ni][0], sc[ni][1]));
            tm1 = fmaxf(tm1, fmaxf(sc[ni][2], sc[ni][3]));
        }
        tm0 *= SS; tm1 *= SS;
        tm0 = fmaxf(tm0, __shfl_xor_sync(0xffffffffu, tm0, 1));
        tm0 = fmaxf(tm0, __shfl_xor_sync(0xffffffffu, tm0, 2));
        tm1 = fmaxf(tm1, __shfl_xor_sync(0xffffffffu, tm1, 1));
        tm1 = fmaxf(tm1, __shfl_xor_sync(0xffffffffu, tm1, 2));

        float m0n = fmaxf(m0, tm0), m1n = fmaxf(m1, tm1);
        float c0 = ex2(m0 - m0n), c1 = ex2(m1 - m1n);
        m0 = m0n; m1 = m1n;
        l0 *= c0; l1 *= c1;
        #pragma unroll
        for (int nd = 0; nd < 8; nd++) {
            ao[nd][0] *= c0; ao[nd][1] *= c0;
            ao[nd][2] *= c1; ao[nd][3] *= c1;
        }

        #pragma unroll
        for (int ni = 0; ni < 8; ni++) {
            sc[ni][0] = ex2(sc[ni][0] * SS - m0);
            sc[ni][1] = ex2(sc[ni][1] * SS - m0);
            sc[ni][2] = ex2(sc[ni][2] * SS - m1);
            sc[ni][3] = ex2(sc[ni][3] * SS - m1);
            l0 += sc[ni][0] + sc[ni][1];
            l1 += sc[ni][2] + sc[ni][3];
        }

        unsigned pa[4][4];
        #pragma unroll
        for (int ki = 0; ki < 4; ki++) {
            pa[ki][0] = pack_bf16(sc[2 * ki][0],     sc[2 * ki][1]);
            pa[ki][1] = pack_bf16(sc[2 * ki][2],     sc[2 * ki][3]);
            pa[ki][2] = pack_bf16(sc[2 * ki + 1][0], sc[2 * ki + 1][1]);
            pa[ki][3] = pack_bf16(sc[2 * ki + 1][2], sc[2 * ki + 1][3]);
        }

        #pragma unroll
        for (int ki = 0; ki < 4; ki++) {
            const unsigned kb = ki * 32;
            #pragma unroll
            for (int np = 0; np < 4; np++) {
                unsigned bb[4];
                ldsm_x4(bb, sVu + kOff[np] + kb);
                mma_bf16(ao[2 * np],     pa[ki][0], pa[ki][1], pa[ki][2], pa[ki][3], bb[0], bb[1]);
                mma_bf16(ao[2 * np + 1], pa[ki][0], pa[ki][1], pa[ki][2], pa[ki][3], bb[2], bb[3]);
            }
        }

        __syncthreads();
        buf ^= 1;
    }

    l0 += __shfl_xor_sync(0xffffffffu, l0, 1);
    l0 += __shfl_xor_sync(0xffffffffu, l0, 2);
    l1 += __shfl_xor_sync(0xffffffffu, l1, 1);
    l1 += __shfl_xor_sync(0xffffffffu, l1, 2);
    const float inv0 = 1.f / l0, inv1 = 1.f / l1;

    const int b = bh / NH, h = bh % NH;
    const int r0 = q0 + wid * 16 + gq;
    const size_t off0 = ((size_t)b * SEQ + r0) * DMODEL + h * HD;
    const size_t off1 = off0 + 8 * DMODEL;

    #pragma unroll
    for (int nd = 0; nd < 8; nd++) {
        const int col = nd * 8 + gr * 2;
        #pragma unroll
        for (int e = 0; e < 2; e++) {
            float v0 = ao[nd][e]     * inv0 + x[off0 + col + e];
            float v1 = ao[nd][2 + e] * inv1 + x[off1 + col + e];
            __nv_bfloat16 h0 = __float2bfloat16(v0);
            __nv_bfloat16 h1 = __float2bfloat16(v1);
            y1h[off0 + col + e] = h0;
            y1h[off1 + col + e] = h1;
            y1l[off0 + col + e] = __float2bfloat16(v0 - __bfloat162float(h0));
            y1l[off1 + col + e] = __float2bfloat16(v1 - __bfloat162float(h1));
        }
    }
}

// ---------------- LayerNorm ----------------
__inline__ __device__ float warpsum(float v) {
    #pragma unroll
    for (int o = 16; o; o >>= 1) v += __shfl_xor_sync(0xffffffffu, v, o);
    return v;
}

__global__ __launch_bounds__(256)
void ln_kernel(const float* __restrict__ Y, const float* __restrict__ gamma,
               const float* __restrict__ beta, float* __restrict__ out)
{
    const int row = blockIdx.x;
    const int t = threadIdx.x;
    const float* yr = Y + (size_t)row * DMODEL;

    float vals[4];
    float s = 0.f, s2 = 0.f;
    #pragma unroll
    for (int k = 0; k < 4; k++) {
        float v = yr[t + k * 256];
        vals[k] = v;
        s += v; s2 += v * v;
    }
    s = warpsum(s); s2 = warpsum(s2);

    __shared__ float sh[16];
    int w = t >> 5, ln = t & 31;
    if (ln == 0) { sh[w] = s; sh[8 + w] = s2; }
    __syncthreads();
    if (t == 0) {
        float a = 0.f, a2 = 0.f;
        #pragma unroll
        for (int i = 0; i < 8; i++) { a += sh[i]; a2 += sh[8 + i]; }
        sh[0] = a; sh[8] = a2;
    }
    __syncthreads();
    const float mu  = sh[0] * (1.f / DMODEL);
    const float var = sh[8] * (1.f / DMODEL) - mu * mu;
    const float inv = rsqrtf(var + 1e-5f);

    #pragma unroll
    for (int k = 0; k < 4; k++) {
        int c = t + k * 256;
        out[(size_t)row * DMODEL + c] = (vals[k] - mu) * inv * gamma[c] + beta[c];
    }
}

// ---------------- launch ----------------
extern "C" void kernel_launch(void* const* d_in, const int* in_sizes, int n_in,
                              void* d_out, int out_size)
{
    const float* x      = (const float*)d_in[0];
    const float* w_qkv  = (const float*)d_in[1];
    const float* b_qkv  = (const float*)d_in[2];
    const float* w_out  = (const float*)d_in[3];
    const float* b_out  = (const float*)d_in[4];
    const float* gammap = (const float*)d_in[5];
    const float* betap  = (const float*)d_in[6];
    float* out = (float*)d_out;

    float *y2;
    __nv_bfloat16 *xh, *wqh, *woh, *wol, *y1h, *y1l, *qb, *kb, *vt;
    cudaGetSymbolAddress((void**)&y2, g_y2);
    cudaGetSymbolAddress((void**)&xh, g_xh);
    cudaGetSymbolAddress((void**)&wqh, g_wqh);
    cudaGetSymbolAddress((void**)&woh, g_woh);
    cudaGetSymbolAddress((void**)&wol, g_wol);
    cudaGetSymbolAddress((void**)&y1h, g_y1h);
    cudaGetSymbolAddress((void**)&y1l, g_y1l);
    cudaGetSymbolAddress((void**)&qb, g_qb);
    cudaGetSymbolAddress((void**)&kb, g_kb);
    cudaGetSymbolAddress((void**)&vt, g_vt);

    cudaFuncSetAttribute(gemm_mma<0>, cudaFuncAttributeMaxDynamicSharedMemorySize, NSTG * STG_S);
    cudaFuncSetAttribute(gemm_mma<1>, cudaFuncAttributeMaxDynamicSharedMemorySize, NSTG * STG_F);
    cudaFuncSetAttribute(attn_mma, cudaFuncAttributeMaxDynamicSharedMemorySize, 2 * ASTG);

    // operand prep
    to_bf16<<<(ROWS * DMODEL) / 256, 256>>>(x, xh);
    transpose_split<false><<<dim3(3 * DMODEL / 32, DMODEL / 32), 256>>>(w_qkv, wqh, nullptr, DMODEL, 3 * DMODEL);
    transpose_split<true><<<dim3(DMODEL / 32, DMODEL / 32), 256>>>(w_out, woh, wol, DMODEL, DMODEL);

    // 1. QKV projection (1-pass bf16) + fused bias/RoPE/split
    gemm_mma<1><<<dim3(3 * DMODEL / 128, ROWS / 128), 256, NSTG * STG_F>>>(
        xh, nullptr, wqh, nullptr, b_qkv, nullptr, qb, kb, vt, 3 * DMODEL, DMODEL);

    // 2. HMMA flash attention + residual -> y1 hi/lo
    dim3 ga(SEQ / 128, Bsz * NH);
    attn_mma<<<ga, 256, 2 * ASTG>>>(qb, kb, vt, x, y1h, y1l);

    // 3. output projection (3-pass split bf16, fp32-accurate)
    gemm_mma<0><<<dim3(DMODEL / 128, ROWS / 128), 256, NSTG * STG_S>>>(
        y1h, y1l, woh, wol, b_out, y2, nullptr, nullptr, nullptr, DMODEL, DMODEL);

    // 4. layernorm
    ln_kernel<<<ROWS, 256>>>(y2, gammap, betap, out);
}